// round 2
// baseline (speedup 1.0000x reference)
#include <cuda_runtime.h>
#include <math.h>
#include <stdint.h>

// ---------------------------------------------------------------------------
// MoEGate (DeepSeek-V3 noaux_tc router) on GB300 sm_103a
// Round 2: fp32 GEMM with hierarchical + Kahan-compensated accumulation
//          (logit error ~3.5e-7, below the jax reference's own fp32 error, so
//          top-k index decisions match), fp64 sigmoid, conflict-free LDS.128
//          B loads. Then 1-warp-per-row routing top-k kernel.
// ---------------------------------------------------------------------------

#define SEQ     16384
#define HIDDEN  7168
#define NEXP    256
#define NGROUP  8
#define GSIZE   32
#define TOPKG   4
#define TOPK    8
#define RSCALE  2.5f

// 16 MB scratch for sigmoid scores
__device__ float g_scores[(size_t)SEQ * NEXP];

// ----------------------------- GEMM kernel --------------------------------
#define TM 128
#define TN 128
#define TK 16
#define NTHR 256

__device__ __forceinline__ void cp_async4(uint32_t dst, const void* src) {
    asm volatile("cp.async.ca.shared.global [%0], [%1], 4;\n" :: "r"(dst), "l"(src));
}

__global__ __launch_bounds__(NTHR, 1)
void gemm_sigmoid_kernel(const float* __restrict__ A,   // [SEQ, HIDDEN]
                         const float* __restrict__ W)   // [NEXP, HIDDEN]
{
    __shared__ float As[2][TK][TM];
    __shared__ float Bs[2][TK][TN];

    const int tid = threadIdx.x;
    const int tx  = tid & 15;          // 16 col-threads
    const int ty  = tid >> 4;          // 16 row-threads
    const int m0  = blockIdx.y * TM;
    const int n0  = blockIdx.x * TN;

    // Load mapping: thread covers (m = tid&127, k = (tid>>7)*8 + j) for j=0..7
    const int mm = tid & 127;
    const int kk = (tid >> 7) << 3;    // 0 or 8

    const float* aSrc = A + (size_t)(m0 + mm) * HIDDEN + kk;
    const float* bSrc = W + (size_t)(n0 + mm) * HIDDEN + kk;

    // Master (Kahan-compensated) + compensation + inner (per 2-tile window)
    unsigned long long sAcc[8][4], cAcc[8][4], inner[8][4];
    #pragma unroll
    for (int i = 0; i < 8; i++)
        #pragma unroll
        for (int j = 0; j < 4; j++) {
            sAcc[i][j] = 0ULL; cAcc[i][j] = 0ULL; inner[i][j] = 0ULL;
        }

    const uint32_t aBase0 = (uint32_t)__cvta_generic_to_shared(&As[0][kk][mm]);
    const uint32_t bBase0 = (uint32_t)__cvta_generic_to_shared(&Bs[0][kk][mm]);
    const uint32_t bufStrideA = (uint32_t)(TK * TM * 4);
    const uint32_t bufStrideB = (uint32_t)(TK * TN * 4);

    // prologue: tile 0 -> buf 0
    {
        #pragma unroll
        for (int j = 0; j < 8; j++) {
            cp_async4(aBase0 + j * TM * 4, aSrc + j);
            cp_async4(bBase0 + j * TN * 4, bSrc + j);
        }
        asm volatile("cp.async.commit_group;\n");
    }

    const int NT = HIDDEN / TK;     // 448 (even)
    for (int t = 0; t < NT; ++t) {
        const int buf = t & 1;
        if (t + 1 < NT) {
            const int nb = buf ^ 1;
            const float* pa = aSrc + (t + 1) * TK;
            const float* pb = bSrc + (t + 1) * TK;
            const uint32_t da = aBase0 + nb * bufStrideA;
            const uint32_t db = bBase0 + nb * bufStrideB;
            #pragma unroll
            for (int j = 0; j < 8; j++) {
                cp_async4(da + j * TM * 4, pa + j);
                cp_async4(db + j * TN * 4, pb + j);
            }
            asm volatile("cp.async.commit_group;\n");
            asm volatile("cp.async.wait_group 1;\n");
        } else {
            asm volatile("cp.async.wait_group 0;\n");
        }
        __syncthreads();

        #pragma unroll
        for (int k = 0; k < TK; k++) {
            const float4 a0 = *(const float4*)&As[buf][k][ty * 4];
            const float4 a1 = *(const float4*)&As[buf][k][64 + ty * 4];
            // Conflict-free 128-bit B loads (broadcast across half-warps)
            const ulonglong2 bu0 = *(const ulonglong2*)&Bs[buf][k][tx * 4];
            const ulonglong2 bu1 = *(const ulonglong2*)&Bs[buf][k][64 + tx * 4];
            const float av[8] = {a0.x, a0.y, a0.z, a0.w, a1.x, a1.y, a1.z, a1.w};
            const unsigned long long bv[4] = {bu0.x, bu0.y, bu1.x, bu1.y};
            #pragma unroll
            for (int i = 0; i < 8; i++) {
                unsigned long long ad;
                asm("mov.b64 %0, {%1, %1};" : "=l"(ad) : "f"(av[i]));
                #pragma unroll
                for (int j = 0; j < 4; j++) {
                    asm("fma.rn.f32x2 %0, %1, %2, %0;"
                        : "+l"(inner[i][j]) : "l"(ad), "l"(bv[j]));
                }
            }
        }

        // Kahan-merge inner -> (sAcc, cAcc) every 2 tiles (32 k-steps)
        if (t & 1) {
            #pragma unroll
            for (int i = 0; i < 8; i++)
                #pragma unroll
                for (int j = 0; j < 4; j++) {
                    unsigned long long y, tt, z;
                    asm("sub.rn.f32x2 %0, %1, %2;" : "=l"(y)  : "l"(inner[i][j]), "l"(cAcc[i][j]));
                    asm("add.rn.f32x2 %0, %1, %2;" : "=l"(tt) : "l"(sAcc[i][j]),  "l"(y));
                    asm("sub.rn.f32x2 %0, %1, %2;" : "=l"(z)  : "l"(tt),          "l"(sAcc[i][j]));
                    asm("sub.rn.f32x2 %0, %1, %2;" : "=l"(cAcc[i][j]) : "l"(z),   "l"(y));
                    sAcc[i][j] = tt;
                    inner[i][j] = 0ULL;
                }
        }
        __syncthreads();
    }

    // Final logits = sAcc - cAcc; sigmoid in fp64; store to scratch
    union Cvt { unsigned long long u; float2 f; };
    #pragma unroll
    for (int i = 0; i < 8; i++) {
        const int row = m0 + ((i < 4) ? (ty * 4 + i) : (64 + ty * 4 + (i - 4)));
        float v[8];
        #pragma unroll
        for (int j = 0; j < 4; j++) {
            unsigned long long fin;
            asm("sub.rn.f32x2 %0, %1, %2;" : "=l"(fin) : "l"(sAcc[i][j]), "l"(cAcc[i][j]));
            Cvt p; p.u = fin;
            v[j * 2]     = p.f.x;
            v[j * 2 + 1] = p.f.y;
        }
        float o[8];
        #pragma unroll
        for (int j = 0; j < 8; j++) {
            const double sc = 1.0 / (1.0 + exp(-(double)v[j]));
            o[j] = (float)sc;
        }
        float* dst = g_scores + (size_t)row * NEXP + n0;
        *(float4*)(dst + tx * 4)      = make_float4(o[0], o[1], o[2], o[3]);
        *(float4*)(dst + 64 + tx * 4) = make_float4(o[4], o[5], o[6], o[7]);
    }
}

// ----------------------------- Top-k kernel --------------------------------
// One warp per row. Replicates jax.lax.top_k semantics (descending, ties ->
// lower index first) for both group selection and expert selection.
__global__ __launch_bounds__(256)
void topk_kernel(const float* __restrict__ bias,
                 float* __restrict__ out,
                 int write_idx)
{
    const int warp = threadIdx.x >> 5;
    const int lane = threadIdx.x & 31;
    const int row  = blockIdx.x * 8 + warp;
    if (row >= SEQ) return;

    const float* sp = g_scores + (size_t)row * NEXP + lane * 8;
    const float4 sA = *(const float4*)sp;
    const float4 sB = *(const float4*)(sp + 4);
    float s[8] = {sA.x, sA.y, sA.z, sA.w, sB.x, sB.y, sB.z, sB.w};

    float c[8];
    #pragma unroll
    for (int i = 0; i < 8; i++)
        c[i] = s[i] + __ldg(&bias[lane * 8 + i]);

    // --- group top-2 sum (group = 32 experts = 4 lanes; all 8 experts of a
    //     lane are in the same group)
    float m1 = -INFINITY, m2 = -INFINITY;
    #pragma unroll
    for (int i = 0; i < 8; i++) {
        if (c[i] > m1)      { m2 = m1; m1 = c[i]; }
        else if (c[i] > m2) { m2 = c[i]; }
    }
    #pragma unroll
    for (int off = 1; off <= 2; off <<= 1) {
        const float o1 = __shfl_xor_sync(0xFFFFFFFFu, m1, off);
        const float o2 = __shfl_xor_sync(0xFFFFFFFFu, m2, off);
        const float n1 = fmaxf(m1, o1);
        const float n2 = fmaxf(fminf(m1, o1), fmaxf(m2, o2));
        m1 = n1; m2 = n2;
    }
    const float gs = m1 + m2;        // this lane's group score
    const int   g  = lane >> 2;

    // --- rank of this group (strictly greater OR equal-with-lower-index)
    int rank = 0;
    #pragma unroll
    for (int h = 0; h < NGROUP; h++) {
        const float gh = __shfl_sync(0xFFFFFFFFu, gs, h * 4);
        rank += (gh > gs) || (gh == gs && h < g);
    }
    const bool sel = (rank < TOPKG);

    float tmp[8];
    #pragma unroll
    for (int i = 0; i < 8; i++)
        tmp[i] = sel ? c[i] : 0.0f;

    // --- global top-8 over masked corrected scores; gather raw scores
    float wsel[8];
    int   isel[8];
    float wsum = 0.0f;
    #pragma unroll
    for (int t = 0; t < TOPK; t++) {
        float bv = tmp[0];
        int   bi = 0;
        #pragma unroll
        for (int i = 1; i < 8; i++)
            if (tmp[i] > bv) { bv = tmp[i]; bi = i; }
        int   be   = lane * 8 + bi;
        float braw = s[bi];
        #pragma unroll
        for (int off = 16; off; off >>= 1) {
            const float ov  = __shfl_xor_sync(0xFFFFFFFFu, bv, off);
            const int   oe  = __shfl_xor_sync(0xFFFFFFFFu, be, off);
            const float orw = __shfl_xor_sync(0xFFFFFFFFu, braw, off);
            if (ov > bv || (ov == bv && oe < be)) { bv = ov; be = oe; braw = orw; }
        }
        wsel[t] = braw;
        isel[t] = be;
        wsum += braw;
        if ((be >> 3) == lane) tmp[be & 7] = -INFINITY;
    }

    const float invd = RSCALE / (wsum + 1e-20f);
    if (lane == 0) {
        #pragma unroll
        for (int t = 0; t < TOPK; t++)
            out[(size_t)row * TOPK + t] = wsel[t] * invd;
        if (write_idx) {
            #pragma unroll
            for (int t = 0; t < TOPK; t++)
                out[(size_t)SEQ * TOPK + (size_t)row * TOPK + t] = (float)isel[t];
        }
    }
}

// ----------------------------- launch --------------------------------------
extern "C" void kernel_launch(void* const* d_in, const int* in_sizes, int n_in,
                              void* d_out, int out_size)
{
    // Identify inputs by element count for robustness.
    const float* hidden = (const float*)d_in[0];
    const float* weight = (const float*)d_in[1];
    const float* bias   = (const float*)d_in[2];
    for (int i = 0; i < n_in; i++) {
        if (in_sizes[i] == SEQ * HIDDEN)       hidden = (const float*)d_in[i];
        else if (in_sizes[i] == NEXP * HIDDEN) weight = (const float*)d_in[i];
        else if (in_sizes[i] == NEXP)          bias   = (const float*)d_in[i];
    }
    float* out = (float*)d_out;

    dim3 ggrid(NEXP / TN, SEQ / TM);   // (2, 128)
    gemm_sigmoid_kernel<<<ggrid, NTHR>>>(hidden, weight);

    const int write_idx = (out_size >= 2 * SEQ * TOPK) ? 1 : 0;
    topk_kernel<<<SEQ / 8, 256>>>(bias, out, write_idx);
}

// round 6
// speedup vs baseline: 2.2572x; 2.2572x over previous
#include <cuda_runtime.h>
#include <cuda_bf16.h>
#include <math.h>
#include <stdint.h>

// ---------------------------------------------------------------------------
// MoEGate (DeepSeek-V3 noaux_tc router) on GB300 sm_103a (compute_103 PTX)
// Round 6: bf16 3-way-split mma.sync GEMM with magnitude-routed accumulators:
//          h*h -> hh (drained via exact 2Sum into master every 2 tiles,
//          residual -> corr), 5 correction products -> corr (2^-9 scale).
//          Logit error ~1e-7 (< proven-passing round-2 level). fp64 combine +
//          sigmoid -> g_scores, then warp-per-row top-k.
// ---------------------------------------------------------------------------

#define SEQ     16384
#define HIDDEN  7168
#define NEXP    256
#define NGROUP  8
#define TOPKG   4
#define TOPK    8
#define RSCALE  2.5f

#define KTILE   32
#define NTILES  (HIDDEN / KTILE)     // 224
#define NTHR    256

// ---- scratch -----
__device__ float g_scores[(size_t)SEQ * NEXP];
// B split planes: [3][NTILES][256 cols][16 words]; word = bf16 pair, swizzled
#define B_TILE_WORDS  (256 * 16)                       // 4096
#define B_PLANE_WORDS ((size_t)NTILES * B_TILE_WORDS)  // 917504
__device__ __align__(16) uint32_t g_Bsplit[3 * B_PLANE_WORDS];

// ---- smem stage layout (words) ----
#define A_PLANE   2048
#define B_OFF     6144
#define STG_WORDS 12288
#define SMEM_BYTES (2 * STG_WORDS * 4)   // 96 KB

// ------------------------------- helpers -----------------------------------
__device__ __forceinline__ uint16_t bf16u(float x) {
    return __bfloat16_as_ushort(__float2bfloat16_rn(x));
}
__device__ __forceinline__ float bf16f(uint16_t u) {
    return __bfloat162float(__ushort_as_bfloat16(u));
}
__device__ __forceinline__ void split3(float x, uint16_t& s0, uint16_t& s1, uint16_t& s2) {
    s0 = bf16u(x);
    const float r1 = x - bf16f(s0);
    s1 = bf16u(r1);
    const float r2 = r1 - bf16f(s1);
    s2 = bf16u(r2);
}
__device__ __forceinline__ void mma16(float* d, uint32_t a0, uint32_t a1,
                                      uint32_t a2, uint32_t a3,
                                      uint32_t b0, uint32_t b1) {
    asm volatile("mma.sync.aligned.m16n8k16.row.col.f32.bf16.bf16.f32 "
                 "{%0,%1,%2,%3}, {%4,%5,%6,%7}, {%8,%9}, {%0,%1,%2,%3};"
                 : "+f"(d[0]), "+f"(d[1]), "+f"(d[2]), "+f"(d[3])
                 : "r"(a0), "r"(a1), "r"(a2), "r"(a3), "r"(b0), "r"(b1));
}
__device__ __forceinline__ void cp16(uint32_t dst, const void* src) {
    asm volatile("cp.async.cg.shared.global [%0], [%1], 16;" :: "r"(dst), "l"(src));
}
// exact 2Sum: master += hh (exactly); residual accumulated into corr; hh = 0.
// emitted as round-to-nearest asm so no compiler flag can reassociate it.
__device__ __forceinline__ void twosum_acc(float& master, float& corr, float& hh) {
    float a = master, b = hh, s, bp, ap, da, db, r;
    asm("add.rn.f32 %0, %1, %2;" : "=f"(s)  : "f"(a),  "f"(b));
    asm("sub.rn.f32 %0, %1, %2;" : "=f"(bp) : "f"(s),  "f"(a));
    asm("sub.rn.f32 %0, %1, %2;" : "=f"(ap) : "f"(s),  "f"(bp));
    asm("sub.rn.f32 %0, %1, %2;" : "=f"(db) : "f"(b),  "f"(bp));
    asm("sub.rn.f32 %0, %1, %2;" : "=f"(da) : "f"(a),  "f"(ap));
    asm("add.rn.f32 %0, %1, %2;" : "=f"(r)  : "f"(da), "f"(db));
    asm("add.rn.f32 %0, %0, %1;" : "+f"(corr) : "f"(r));
    master = s;
    hh = 0.0f;
}

// ------------------------- W split (pre-swizzled planes) -------------------
__global__ void wsplit_kernel(const float* __restrict__ W) {
    const int n = blockIdx.x;
    const int k = blockIdx.y * 256 + threadIdx.x;
    const float w = W[(size_t)n * HIDDEN + k];
    uint16_t s0, s1, s2;
    split3(w, s0, s1, s2);
    const int t    = k >> 5;
    const int pair = (k & 31) >> 1;
    const int half = k & 1;
    const uint32_t v  = (uint32_t)(((n >> 1) & 3) << 2);
    const uint32_t wi = (size_t)t * B_TILE_WORDS + (uint32_t)n * 16u
                        + ((uint32_t)pair ^ v);
    uint16_t* base = (uint16_t*)g_Bsplit;
    base[(size_t)0 * B_PLANE_WORDS * 2 + (size_t)wi * 2 + half] = s0;
    base[(size_t)1 * B_PLANE_WORDS * 2 + (size_t)wi * 2 + half] = s1;
    base[(size_t)2 * B_PLANE_WORDS * 2 + (size_t)wi * 2 + half] = s2;
}

// ------------------------------- GEMM kernel -------------------------------
__global__ __launch_bounds__(NTHR, 1)
void gemm_bf16_kernel(const float* __restrict__ A) {
    extern __shared__ uint32_t sm[];
    const int tid  = threadIdx.x;
    const int wid  = tid >> 5;
    const int lane = tid & 31;
    const int n0   = blockIdx.x * 128;
    const int m0   = blockIdx.y * 128;

    // ---- staging mappings
    const int r = tid >> 1;
    const int h = tid & 1;
    const float* aPtr = A + (size_t)(m0 + r) * HIDDEN + h * 16;
    const uint32_t vr = (uint32_t)(((r >> 1) & 3) << 2);
    const uint32_t aw0 = (uint32_t)r * 16u + ((uint32_t)(8 * h) ^ vr);
    const uint32_t aw1 = (uint32_t)r * 16u + ((uint32_t)(8 * h + 4) ^ vr);

    const uint32_t bCopyOff = (uint32_t)tid * 8u;
    uint32_t smAddr;
    asm("{ .reg .u64 t; cvta.to.shared.u64 t, %1; cvt.u32.u64 %0, t; }"
        : "=r"(smAddr) : "l"((const void*)sm));

    // ---- frag mappings
    const int qq = lane >> 2;
    const int c  = lane & 3;
    const uint32_t v = (uint32_t)(((qq >> 1) & 3) << 2);
    const uint32_t aRowW  = ((uint32_t)wid * 16 + (uint32_t)qq) * 16u;
    const uint32_t bColW  = (uint32_t)qq * 16u;

    float hh[16][4];        // h*h accumulator (drained every 2 tiles)
    float corr[16][4];      // correction products + 2Sum residuals
    float master[16][4];    // exact running sum of hh drains
    #pragma unroll
    for (int nf = 0; nf < 16; nf++)
        #pragma unroll
        for (int j = 0; j < 4; j++) {
            hh[nf][j] = 0.0f; corr[nf][j] = 0.0f; master[nf][j] = 0.0f;
        }

    auto stageA = [&](uint32_t* dst, const float4* pf) {
        uint32_t pk[3][8];
        #pragma unroll
        for (int j = 0; j < 4; j++) {
            const float4 vv = pf[j];
            uint16_t a0, a1, a2, b0, b1, b2, c0, c1, c2, d0, d1, d2;
            split3(vv.x, a0, a1, a2);
            split3(vv.y, b0, b1, b2);
            split3(vv.z, c0, c1, c2);
            split3(vv.w, d0, d1, d2);
            pk[0][j*2]   = (uint32_t)a0 | ((uint32_t)b0 << 16);
            pk[0][j*2+1] = (uint32_t)c0 | ((uint32_t)d0 << 16);
            pk[1][j*2]   = (uint32_t)a1 | ((uint32_t)b1 << 16);
            pk[1][j*2+1] = (uint32_t)c1 | ((uint32_t)d1 << 16);
            pk[2][j*2]   = (uint32_t)a2 | ((uint32_t)b2 << 16);
            pk[2][j*2+1] = (uint32_t)c2 | ((uint32_t)d2 << 16);
        }
        #pragma unroll
        for (int p = 0; p < 3; p++) {
            *(uint4*)&dst[p * A_PLANE + aw0] =
                make_uint4(pk[p][0], pk[p][1], pk[p][2], pk[p][3]);
            *(uint4*)&dst[p * A_PLANE + aw1] =
                make_uint4(pk[p][4], pk[p][5], pk[p][6], pk[p][7]);
        }
    };
    auto stageB = [&](uint32_t stageByteAddr, int t) {
        #pragma unroll
        for (int p = 0; p < 3; p++) {
            const uint32_t* src = g_Bsplit + (size_t)p * B_PLANE_WORDS
                                + (size_t)t * B_TILE_WORDS + (uint32_t)n0 * 16u
                                + bCopyOff;
            const uint32_t dst = stageByteAddr + (B_OFF + p * A_PLANE + bCopyOff) * 4u;
            cp16(dst,      src);
            cp16(dst + 16, src + 4);
        }
        asm volatile("cp.async.commit_group;");
    };

    // ---- prologue
    float4 pf[4];
    #pragma unroll
    for (int j = 0; j < 4; j++) pf[j] = *(const float4*)(aPtr + j * 4);
    stageB(smAddr, 0);
    stageA(sm, pf);
    #pragma unroll
    for (int j = 0; j < 4; j++) pf[j] = *(const float4*)(aPtr + KTILE + j * 4);

    #pragma unroll 1
    for (int t = 0; t < NTILES; ++t) {
        uint32_t* S = sm + (t & 1) * STG_WORDS;
        __syncthreads();

        if (t + 1 < NTILES) {
            uint32_t* Sn = sm + ((t + 1) & 1) * STG_WORDS;
            stageB(smAddr + (uint32_t)(((t + 1) & 1) * STG_WORDS) * 4u, t + 1);
            stageA(Sn, pf);
            if (t + 2 < NTILES) {
                const float* ap = aPtr + (size_t)(t + 2) * KTILE;
                #pragma unroll
                for (int j = 0; j < 4; j++) pf[j] = *(const float4*)(ap + j * 4);
            }
            asm volatile("cp.async.wait_group 1;");
        } else {
            asm volatile("cp.async.wait_group 0;");
        }
        __syncthreads();

        // ---- 2 k-steps (k16): 1 big product -> hh, 5 corrections -> corr
        #pragma unroll
        for (int ks = 0; ks < 2; ks++) {
            const uint32_t o1 = ((uint32_t)(8 * ks + c)) ^ v;
            const uint32_t o2 = o1 ^ 4u;
            uint32_t A0[3][4];
            #pragma unroll
            for (int p = 0; p < 3; p++) {
                A0[p][0] = S[p * A_PLANE + aRowW + o1];
                A0[p][1] = S[p * A_PLANE + aRowW + 128 + o1];
                A0[p][2] = S[p * A_PLANE + aRowW + o2];
                A0[p][3] = S[p * A_PLANE + aRowW + 128 + o2];
            }
            #pragma unroll
            for (int nf = 0; nf < 16; nf++) {
                const uint32_t bb = B_OFF + bColW + (uint32_t)nf * 128u;
                const uint32_t b00 = S[bb + o1];
                const uint32_t b01 = S[bb + o2];
                const uint32_t b10 = S[A_PLANE + bb + o1];
                const uint32_t b11 = S[A_PLANE + bb + o2];
                const uint32_t b20 = S[2 * A_PLANE + bb + o1];
                const uint32_t b21 = S[2 * A_PLANE + bb + o2];
                mma16(hh[nf],   A0[0][0], A0[0][1], A0[0][2], A0[0][3], b00, b01); // h*h
                mma16(corr[nf], A0[0][0], A0[0][1], A0[0][2], A0[0][3], b10, b11); // h*m
                mma16(corr[nf], A0[1][0], A0[1][1], A0[1][2], A0[1][3], b00, b01); // m*h
                mma16(corr[nf], A0[0][0], A0[0][1], A0[0][2], A0[0][3], b20, b21); // h*l
                mma16(corr[nf], A0[2][0], A0[2][1], A0[2][2], A0[2][3], b00, b01); // l*h
                mma16(corr[nf], A0[1][0], A0[1][1], A0[1][2], A0[1][3], b10, b11); // m*m
            }
        }

        // ---- exact drain hh -> master every 2 tiles (112x)
        if (t & 1) {
            #pragma unroll
            for (int nf = 0; nf < 16; nf++)
                #pragma unroll
                for (int j = 0; j < 4; j++)
                    twosum_acc(master[nf][j], corr[nf][j], hh[nf][j]);
        }
    }

    // ---- epilogue: fp64 combine + sigmoid, direct stores
    const int r1 = m0 + wid * 16 + qq;
    const int r2 = r1 + 8;
    #pragma unroll
    for (int nf = 0; nf < 16; nf++) {
        const int cc = n0 + nf * 8 + c * 2;
        double lg[4];
        #pragma unroll
        for (int j = 0; j < 4; j++)
            lg[j] = (double)master[nf][j] + (double)corr[nf][j];
        float2 v1, v2;
        v1.x = (float)(1.0 / (1.0 + exp(-lg[0])));
        v1.y = (float)(1.0 / (1.0 + exp(-lg[1])));
        v2.x = (float)(1.0 / (1.0 + exp(-lg[2])));
        v2.y = (float)(1.0 / (1.0 + exp(-lg[3])));
        *(float2*)&g_scores[(size_t)r1 * NEXP + cc] = v1;
        *(float2*)&g_scores[(size_t)r2 * NEXP + cc] = v2;
    }
}

// ----------------------------- Top-k kernel --------------------------------
__global__ __launch_bounds__(256)
void topk_kernel(const float* __restrict__ bias,
                 float* __restrict__ out,
                 int write_idx)
{
    const int warp = threadIdx.x >> 5;
    const int lane = threadIdx.x & 31;
    const int row  = blockIdx.x * 8 + warp;
    if (row >= SEQ) return;

    const float* sp = g_scores + (size_t)row * NEXP + lane * 8;
    const float4 sA = *(const float4*)sp;
    const float4 sB = *(const float4*)(sp + 4);
    float sv[8] = {sA.x, sA.y, sA.z, sA.w, sB.x, sB.y, sB.z, sB.w};

    float c[8];
    #pragma unroll
    for (int i = 0; i < 8; i++)
        c[i] = sv[i] + __ldg(&bias[lane * 8 + i]);

    float m1 = -INFINITY, m2 = -INFINITY;
    #pragma unroll
    for (int i = 0; i < 8; i++) {
        if (c[i] > m1)      { m2 = m1; m1 = c[i]; }
        else if (c[i] > m2) { m2 = c[i]; }
    }
    #pragma unroll
    for (int off = 1; off <= 2; off <<= 1) {
        const float o1 = __shfl_xor_sync(0xFFFFFFFFu, m1, off);
        const float o2 = __shfl_xor_sync(0xFFFFFFFFu, m2, off);
        const float n1 = fmaxf(m1, o1);
        const float n2 = fmaxf(fminf(m1, o1), fmaxf(m2, o2));
        m1 = n1; m2 = n2;
    }
    const float gs = m1 + m2;
    const int   g  = lane >> 2;

    int rank = 0;
    #pragma unroll
    for (int hh = 0; hh < NGROUP; hh++) {
        const float gh = __shfl_sync(0xFFFFFFFFu, gs, hh * 4);
        rank += (gh > gs) || (gh == gs && hh < g);
    }
    const bool sel = (rank < TOPKG);

    float tmp[8];
    #pragma unroll
    for (int i = 0; i < 8; i++)
        tmp[i] = sel ? c[i] : 0.0f;

    float wsel[8];
    int   isel[8];
    float wsum = 0.0f;
    #pragma unroll
    for (int t = 0; t < TOPK; t++) {
        float bv = tmp[0];
        int   bi = 0;
        #pragma unroll
        for (int i = 1; i < 8; i++)
            if (tmp[i] > bv) { bv = tmp[i]; bi = i; }
        int   be   = lane * 8 + bi;
        float braw = sv[bi];
        #pragma unroll
        for (int off = 16; off; off >>= 1) {
            const float ov  = __shfl_xor_sync(0xFFFFFFFFu, bv, off);
            const int   oe  = __shfl_xor_sync(0xFFFFFFFFu, be, off);
            const float orw = __shfl_xor_sync(0xFFFFFFFFu, braw, off);
            if (ov > bv || (ov == bv && oe < be)) { bv = ov; be = oe; braw = orw; }
        }
        wsel[t] = braw;
        isel[t] = be;
        wsum += braw;
        if ((be >> 3) == lane) tmp[be & 7] = -INFINITY;
    }

    const float invd = RSCALE / (wsum + 1e-20f);
    if (lane == 0) {
        #pragma unroll
        for (int t = 0; t < TOPK; t++)
            out[(size_t)row * TOPK + t] = wsel[t] * invd;
        if (write_idx) {
            #pragma unroll
            for (int t = 0; t < TOPK; t++)
                out[(size_t)SEQ * TOPK + (size_t)row * TOPK + t] = (float)isel[t];
        }
    }
}

// ----------------------------- launch --------------------------------------
extern "C" void kernel_launch(void* const* d_in, const int* in_sizes, int n_in,
                              void* d_out, int out_size)
{
    const float* hidden = (const float*)d_in[0];
    const float* weight = (const float*)d_in[1];
    const float* bias   = (const float*)d_in[2];
    for (int i = 0; i < n_in; i++) {
        if (in_sizes[i] == SEQ * HIDDEN)       hidden = (const float*)d_in[i];
        else if (in_sizes[i] == NEXP * HIDDEN) weight = (const float*)d_in[i];
        else if (in_sizes[i] == NEXP)          bias   = (const float*)d_in[i];
    }
    float* out = (float*)d_out;

    cudaFuncSetAttribute(gemm_bf16_kernel,
                         cudaFuncAttributeMaxDynamicSharedMemorySize, SMEM_BYTES);

    wsplit_kernel<<<dim3(NEXP, HIDDEN / 256), 256>>>(weight);
    gemm_bf16_kernel<<<dim3(NEXP / 128, SEQ / 128), NTHR, SMEM_BYTES>>>(hidden);

    const int write_idx = (out_size >= 2 * SEQ * TOPK) ? 1 : 0;
    topk_kernel<<<SEQ / 8, 256>>>(bias, out, write_idx);
}

// round 7
// speedup vs baseline: 2.8262x; 1.2521x over previous
#include <cuda_runtime.h>
#include <cuda_fp16.h>
#include <math.h>
#include <stdint.h>

// ---------------------------------------------------------------------------
// MoEGate (DeepSeek-V3 noaux_tc router) on GB300 sm_103a (compute_103 PTX)
// Round 7: fp16 2-way-split mma.sync GEMM, 4 products/k-step (vs round-6's
//          bf16 6-product): hh = a0*b0 (2Sum-drained exactly, residual*2^12
//          -> corr), corr += a0*b1 + a1*b0 + a1*(b1*2^-12). Weights scaled
//          by 64 so all fp16 chunks are normal. Logit err ~1.6e-7.
//          fp64 combine+sigmoid -> g_scores, warp-per-row top-k.
// ---------------------------------------------------------------------------

#define SEQ     16384
#define HIDDEN  7168
#define NEXP    256
#define NGROUP  8
#define TOPKG   4
#define TOPK    8
#define RSCALE  2.5f

#define KTILE   32
#define NTILES  (HIDDEN / KTILE)     // 224
#define NTHR    256

// ---- scratch -----
__device__ float g_scores[(size_t)SEQ * NEXP];
// B split planes: [3][NTILES][256 cols][16 words]; word = fp16 pair, swizzled
#define B_TILE_WORDS  (256 * 16)                       // 4096
#define B_PLANE_WORDS ((size_t)NTILES * B_TILE_WORDS)  // 917504
__device__ __align__(16) uint32_t g_Bsplit[3 * B_PLANE_WORDS];

// ---- smem stage layout (words) ----
// A planes: p*2048 for p in {0,1}; B planes: B_OFF + p*2048 for p in {0,1,2}
#define PLANE     2048
#define B_OFF     4096
#define STG_WORDS 10240
#define SMEM_BYTES (2 * STG_WORDS * 4)   // 80 KB

// ------------------------------- helpers -----------------------------------
__device__ __forceinline__ uint16_t f16u(float x) {
    return __half_as_ushort(__float2half_rn(x));
}
__device__ __forceinline__ float f16f(uint16_t u) {
    return __half2float(__ushort_as_half(u));
}
// 2-way fp16 split: x ~= s0 + s1 * 2^-12  (residual ~2^-24 |x|)
__device__ __forceinline__ void split2(float x, uint16_t& s0, uint16_t& s1) {
    s0 = f16u(x);
    const float r = x - f16f(s0);       // exact (Sterbenz)
    s1 = f16u(r * 4096.0f);
}
__device__ __forceinline__ void mma16(float* d, uint32_t a0, uint32_t a1,
                                      uint32_t a2, uint32_t a3,
                                      uint32_t b0, uint32_t b1) {
    asm volatile("mma.sync.aligned.m16n8k16.row.col.f32.f16.f16.f32 "
                 "{%0,%1,%2,%3}, {%4,%5,%6,%7}, {%8,%9}, {%0,%1,%2,%3};"
                 : "+f"(d[0]), "+f"(d[1]), "+f"(d[2]), "+f"(d[3])
                 : "r"(a0), "r"(a1), "r"(a2), "r"(a3), "r"(b0), "r"(b1));
}
__device__ __forceinline__ void cp16(uint32_t dst, const void* src) {
    asm volatile("cp.async.cg.shared.global [%0], [%1], 16;" :: "r"(dst), "l"(src));
}
// exact 2Sum: master += hh; residual * 4096 accumulated into corr; hh = 0.
// (*4096 rescales the residual to corr's 2^-12 scale; power-of-2 => exact)
__device__ __forceinline__ void twosum_acc(float& master, float& corr, float& hh) {
    float a = master, b = hh, s, bp, ap, da, db, r;
    asm("add.rn.f32 %0, %1, %2;" : "=f"(s)  : "f"(a),  "f"(b));
    asm("sub.rn.f32 %0, %1, %2;" : "=f"(bp) : "f"(s),  "f"(a));
    asm("sub.rn.f32 %0, %1, %2;" : "=f"(ap) : "f"(s),  "f"(bp));
    asm("sub.rn.f32 %0, %1, %2;" : "=f"(db) : "f"(b),  "f"(bp));
    asm("sub.rn.f32 %0, %1, %2;" : "=f"(da) : "f"(a),  "f"(ap));
    asm("add.rn.f32 %0, %1, %2;" : "=f"(r)  : "f"(da), "f"(db));
    asm("fma.rn.f32 %0, %1, 0f45800000, %0;" : "+f"(corr) : "f"(r)); // corr += r*4096
    master = s;
    hh = 0.0f;
}

// ------------------------- W split (pre-swizzled planes) -------------------
// plane0 = fp16(64w), plane1 = fp16((64w - p0)*2^12), plane2 = fp16(p1*2^-12)
__global__ void wsplit_kernel(const float* __restrict__ W) {
    const int n = blockIdx.x;
    const int k = blockIdx.y * 256 + threadIdx.x;
    const float bp = W[(size_t)n * HIDDEN + k] * 64.0f;
    uint16_t s0, s1;
    split2(bp, s0, s1);
    const uint16_t s2 = f16u(f16f(s1) * (1.0f / 4096.0f));
    const int t    = k >> 5;
    const int pair = (k & 31) >> 1;
    const int half = k & 1;
    const uint32_t v  = (uint32_t)(((n >> 1) & 3) << 2);
    const uint32_t wi = (size_t)t * B_TILE_WORDS + (uint32_t)n * 16u
                        + ((uint32_t)pair ^ v);
    uint16_t* base = (uint16_t*)g_Bsplit;
    base[(size_t)0 * B_PLANE_WORDS * 2 + (size_t)wi * 2 + half] = s0;
    base[(size_t)1 * B_PLANE_WORDS * 2 + (size_t)wi * 2 + half] = s1;
    base[(size_t)2 * B_PLANE_WORDS * 2 + (size_t)wi * 2 + half] = s2;
}

// ------------------------------- GEMM kernel -------------------------------
__global__ __launch_bounds__(NTHR, 1)
void gemm_fp16_kernel(const float* __restrict__ A) {
    extern __shared__ uint32_t sm[];
    const int tid  = threadIdx.x;
    const int wid  = tid >> 5;
    const int lane = tid & 31;
    const int n0   = blockIdx.x * 128;
    const int m0   = blockIdx.y * 128;

    // ---- staging mappings
    const int r = tid >> 1;
    const int h = tid & 1;
    const float* aPtr = A + (size_t)(m0 + r) * HIDDEN + h * 16;
    const uint32_t vr = (uint32_t)(((r >> 1) & 3) << 2);
    const uint32_t aw0 = (uint32_t)r * 16u + ((uint32_t)(8 * h) ^ vr);
    const uint32_t aw1 = (uint32_t)r * 16u + ((uint32_t)(8 * h + 4) ^ vr);

    const uint32_t bCopyOff = (uint32_t)tid * 8u;
    uint32_t smAddr;
    asm("{ .reg .u64 t; cvta.to.shared.u64 t, %1; cvt.u32.u64 %0, t; }"
        : "=r"(smAddr) : "l"((const void*)sm));

    // ---- frag mappings
    const int qq = lane >> 2;
    const int c  = lane & 3;
    const uint32_t v = (uint32_t)(((qq >> 1) & 3) << 2);
    const uint32_t aRowW  = ((uint32_t)wid * 16 + (uint32_t)qq) * 16u;
    const uint32_t bColW  = (uint32_t)qq * 16u;

    float hh[16][4];        // a0*b0 accumulator (2Sum-drained every 2 tiles)
    float corr[16][4];      // 2^-12-scale corrections + scaled 2Sum residuals
    float master[16][4];    // exact running sum of hh drains
    #pragma unroll
    for (int nf = 0; nf < 16; nf++)
        #pragma unroll
        for (int j = 0; j < 4; j++) {
            hh[nf][j] = 0.0f; corr[nf][j] = 0.0f; master[nf][j] = 0.0f;
        }

    auto stageA = [&](uint32_t* dst, const float4* pf) {
        uint32_t pk[2][8];
        #pragma unroll
        for (int j = 0; j < 4; j++) {
            const float4 vv = pf[j];
            uint16_t a0, a1, b0, b1, c0, c1, d0, d1;
            split2(vv.x, a0, a1);
            split2(vv.y, b0, b1);
            split2(vv.z, c0, c1);
            split2(vv.w, d0, d1);
            pk[0][j*2]   = (uint32_t)a0 | ((uint32_t)b0 << 16);
            pk[0][j*2+1] = (uint32_t)c0 | ((uint32_t)d0 << 16);
            pk[1][j*2]   = (uint32_t)a1 | ((uint32_t)b1 << 16);
            pk[1][j*2+1] = (uint32_t)c1 | ((uint32_t)d1 << 16);
        }
        #pragma unroll
        for (int p = 0; p < 2; p++) {
            *(uint4*)&dst[p * PLANE + aw0] =
                make_uint4(pk[p][0], pk[p][1], pk[p][2], pk[p][3]);
            *(uint4*)&dst[p * PLANE + aw1] =
                make_uint4(pk[p][4], pk[p][5], pk[p][6], pk[p][7]);
        }
    };
    auto stageB = [&](uint32_t stageByteAddr, int t) {
        #pragma unroll
        for (int p = 0; p < 3; p++) {
            const uint32_t* src = g_Bsplit + (size_t)p * B_PLANE_WORDS
                                + (size_t)t * B_TILE_WORDS + (uint32_t)n0 * 16u
                                + bCopyOff;
            const uint32_t dst = stageByteAddr + (B_OFF + p * PLANE + bCopyOff) * 4u;
            cp16(dst,      src);
            cp16(dst + 16, src + 4);
        }
        asm volatile("cp.async.commit_group;");
    };

    // ---- prologue
    float4 pf[4];
    #pragma unroll
    for (int j = 0; j < 4; j++) pf[j] = *(const float4*)(aPtr + j * 4);
    stageB(smAddr, 0);
    stageA(sm, pf);
    #pragma unroll
    for (int j = 0; j < 4; j++) pf[j] = *(const float4*)(aPtr + KTILE + j * 4);

    #pragma unroll 1
    for (int t = 0; t < NTILES; ++t) {
        uint32_t* S = sm + (t & 1) * STG_WORDS;
        __syncthreads();

        if (t + 1 < NTILES) {
            uint32_t* Sn = sm + ((t + 1) & 1) * STG_WORDS;
            stageB(smAddr + (uint32_t)(((t + 1) & 1) * STG_WORDS) * 4u, t + 1);
            stageA(Sn, pf);
            if (t + 2 < NTILES) {
                const float* ap = aPtr + (size_t)(t + 2) * KTILE;
                #pragma unroll
                for (int j = 0; j < 4; j++) pf[j] = *(const float4*)(ap + j * 4);
            }
            asm volatile("cp.async.wait_group 1;");
        } else {
            asm volatile("cp.async.wait_group 0;");
        }
        __syncthreads();

        // ---- 2 k-steps (k16): 1 big product -> hh, 3 corrections -> corr
        #pragma unroll
        for (int ks = 0; ks < 2; ks++) {
            const uint32_t o1 = ((uint32_t)(8 * ks + c)) ^ v;
            const uint32_t o2 = o1 ^ 4u;
            uint32_t A0[2][4];
            #pragma unroll
            for (int p = 0; p < 2; p++) {
                A0[p][0] = S[p * PLANE + aRowW + o1];
                A0[p][1] = S[p * PLANE + aRowW + 128 + o1];
                A0[p][2] = S[p * PLANE + aRowW + o2];
                A0[p][3] = S[p * PLANE + aRowW + 128 + o2];
            }
            #pragma unroll
            for (int nf = 0; nf < 16; nf++) {
                const uint32_t bb = B_OFF + bColW + (uint32_t)nf * 128u;
                const uint32_t b00 = S[bb + o1];
                const uint32_t b01 = S[bb + o2];
                const uint32_t b10 = S[PLANE + bb + o1];
                const uint32_t b11 = S[PLANE + bb + o2];
                const uint32_t b20 = S[2 * PLANE + bb + o1];
                const uint32_t b21 = S[2 * PLANE + bb + o2];
                mma16(hh[nf],   A0[0][0], A0[0][1], A0[0][2], A0[0][3], b00, b01); // a0*b0
                mma16(corr[nf], A0[0][0], A0[0][1], A0[0][2], A0[0][3], b10, b11); // a0*b1
                mma16(corr[nf], A0[1][0], A0[1][1], A0[1][2], A0[1][3], b00, b01); // a1*b0
                mma16(corr[nf], A0[1][0], A0[1][1], A0[1][2], A0[1][3], b20, b21); // a1*b1*2^-12
            }
        }

        // ---- exact drain hh -> master every 2 tiles (112x)
        if (t & 1) {
            #pragma unroll
            for (int nf = 0; nf < 16; nf++)
                #pragma unroll
                for (int j = 0; j < 4; j++)
                    twosum_acc(master[nf][j], corr[nf][j], hh[nf][j]);
        }
    }

    // ---- epilogue: fp64 combine (undo scales) + sigmoid, direct stores
    const int r1 = m0 + wid * 16 + qq;
    const int r2 = r1 + 8;
    #pragma unroll
    for (int nf = 0; nf < 16; nf++) {
        const int cc = n0 + nf * 8 + c * 2;
        double lg[4];
        #pragma unroll
        for (int j = 0; j < 4; j++)
            lg[j] = ((double)master[nf][j]
                   + (double)corr[nf][j] * (1.0 / 4096.0)) * (1.0 / 64.0);
        float2 v1, v2;
        v1.x = (float)(1.0 / (1.0 + exp(-lg[0])));
        v1.y = (float)(1.0 / (1.0 + exp(-lg[1])));
        v2.x = (float)(1.0 / (1.0 + exp(-lg[2])));
        v2.y = (float)(1.0 / (1.0 + exp(-lg[3])));
        *(float2*)&g_scores[(size_t)r1 * NEXP + cc] = v1;
        *(float2*)&g_scores[(size_t)r2 * NEXP + cc] = v2;
    }
}

// ----------------------------- Top-k kernel --------------------------------
__global__ __launch_bounds__(256)
void topk_kernel(const float* __restrict__ bias,
                 float* __restrict__ out,
                 int write_idx)
{
    const int warp = threadIdx.x >> 5;
    const int lane = threadIdx.x & 31;
    const int row  = blockIdx.x * 8 + warp;
    if (row >= SEQ) return;

    const float* sp = g_scores + (size_t)row * NEXP + lane * 8;
    const float4 sA = *(const float4*)sp;
    const float4 sB = *(const float4*)(sp + 4);
    float sv[8] = {sA.x, sA.y, sA.z, sA.w, sB.x, sB.y, sB.z, sB.w};

    float c[8];
    #pragma unroll
    for (int i = 0; i < 8; i++)
        c[i] = sv[i] + __ldg(&bias[lane * 8 + i]);

    float m1 = -INFINITY, m2 = -INFINITY;
    #pragma unroll
    for (int i = 0; i < 8; i++) {
        if (c[i] > m1)      { m2 = m1; m1 = c[i]; }
        else if (c[i] > m2) { m2 = c[i]; }
    }
    #pragma unroll
    for (int off = 1; off <= 2; off <<= 1) {
        const float o1 = __shfl_xor_sync(0xFFFFFFFFu, m1, off);
        const float o2 = __shfl_xor_sync(0xFFFFFFFFu, m2, off);
        const float n1 = fmaxf(m1, o1);
        const float n2 = fmaxf(fminf(m1, o1), fmaxf(m2, o2));
        m1 = n1; m2 = n2;
    }
    const float gs = m1 + m2;
    const int   g  = lane >> 2;

    int rank = 0;
    #pragma unroll
    for (int hh = 0; hh < NGROUP; hh++) {
        const float gh = __shfl_sync(0xFFFFFFFFu, gs, hh * 4);
        rank += (gh > gs) || (gh == gs && hh < g);
    }
    const bool sel = (rank < TOPKG);

    float tmp[8];
    #pragma unroll
    for (int i = 0; i < 8; i++)
        tmp[i] = sel ? c[i] : 0.0f;

    float wsel[8];
    int   isel[8];
    float wsum = 0.0f;
    #pragma unroll
    for (int t = 0; t < TOPK; t++) {
        float bv = tmp[0];
        int   bi = 0;
        #pragma unroll
        for (int i = 1; i < 8; i++)
            if (tmp[i] > bv) { bv = tmp[i]; bi = i; }
        int   be   = lane * 8 + bi;
        float braw = sv[bi];
        #pragma unroll
        for (int off = 16; off; off >>= 1) {
            const float ov  = __shfl_xor_sync(0xFFFFFFFFu, bv, off);
            const int   oe  = __shfl_xor_sync(0xFFFFFFFFu, be, off);
            const float orw = __shfl_xor_sync(0xFFFFFFFFu, braw, off);
            if (ov > bv || (ov == bv && oe < be)) { bv = ov; be = oe; braw = orw; }
        }
        wsel[t] = braw;
        isel[t] = be;
        wsum += braw;
        if ((be >> 3) == lane) tmp[be & 7] = -INFINITY;
    }

    const float invd = RSCALE / (wsum + 1e-20f);
    if (lane == 0) {
        #pragma unroll
        for (int t = 0; t < TOPK; t++)
            out[(size_t)row * TOPK + t] = wsel[t] * invd;
        if (write_idx) {
            #pragma unroll
            for (int t = 0; t < TOPK; t++)
                out[(size_t)SEQ * TOPK + (size_t)row * TOPK + t] = (float)isel[t];
        }
    }
}

// ----------------------------- launch --------------------------------------
extern "C" void kernel_launch(void* const* d_in, const int* in_sizes, int n_in,
                              void* d_out, int out_size)
{
    const float* hidden = (const float*)d_in[0];
    const float* weight = (const float*)d_in[1];
    const float* bias   = (const float*)d_in[2];
    for (int i = 0; i < n_in; i++) {
        if (in_sizes[i] == SEQ * HIDDEN)       hidden = (const float*)d_in[i];
        else if (in_sizes[i] == NEXP * HIDDEN) weight = (const float*)d_in[i];
        else if (in_sizes[i] == NEXP)          bias   = (const float*)d_in[i];
    }
    float* out = (float*)d_out;

    cudaFuncSetAttribute(gemm_fp16_kernel,
                         cudaFuncAttributeMaxDynamicSharedMemorySize, SMEM_BYTES);

    wsplit_kernel<<<dim3(NEXP, HIDDEN / 256), 256>>>(weight);
    gemm_fp16_kernel<<<dim3(NEXP / 128, SEQ / 128), NTHR, SMEM_BYTES>>>(hidden);

    const int write_idx = (out_size >= 2 * SEQ * TOPK) ? 1 : 0;
    topk_kernel<<<SEQ / 8, 256>>>(bias, out, write_idx);
}

// round 8
// speedup vs baseline: 3.0713x; 1.0867x over previous
#include <cuda_runtime.h>
#include <cuda_fp16.h>
#include <math.h>
#include <stdint.h>

// ---------------------------------------------------------------------------
// MoEGate (DeepSeek-V3 noaux_tc router) on GB300 sm_103a (compute_103 PTX)
// Round 8: round-7 fp16 2-way-split scheme with warp re-tiling 4m x 2n
//          (warp tile m32n64: halves per-warp B smem traffic -> crossbar
//          1.63x cut) and 2Sum drain every 4 tiles (halves drain fma cost).
//          Same 1024 HMMA/tile. Logit err ~1.4e-7 (flip threshold ~6e-7).
// ---------------------------------------------------------------------------

#define SEQ     16384
#define HIDDEN  7168
#define NEXP    256
#define NGROUP  8
#define TOPKG   4
#define TOPK    8
#define RSCALE  2.5f

#define KTILE   32
#define NTILES  (HIDDEN / KTILE)     // 224
#define NTHR    256

// ---- scratch -----
__device__ float g_scores[(size_t)SEQ * NEXP];
// B split planes: [3][NTILES][256 cols][16 words]; word = fp16 pair, swizzled
#define B_TILE_WORDS  (256 * 16)                       // 4096
#define B_PLANE_WORDS ((size_t)NTILES * B_TILE_WORDS)  // 917504
__device__ __align__(16) uint32_t g_Bsplit[3 * B_PLANE_WORDS];

// ---- smem stage layout (words) ----
#define PLANE     2048
#define B_OFF     4096
#define STG_WORDS 10240
#define SMEM_BYTES (2 * STG_WORDS * 4)   // 80 KB

// ------------------------------- helpers -----------------------------------
__device__ __forceinline__ uint16_t f16u(float x) {
    return __half_as_ushort(__float2half_rn(x));
}
__device__ __forceinline__ float f16f(uint16_t u) {
    return __half2float(__ushort_as_half(u));
}
// 2-way fp16 split: x ~= s0 + s1 * 2^-12  (residual ~2^-24 |x|)
__device__ __forceinline__ void split2(float x, uint16_t& s0, uint16_t& s1) {
    s0 = f16u(x);
    const float r = x - f16f(s0);       // exact (Sterbenz)
    s1 = f16u(r * 4096.0f);
}
__device__ __forceinline__ void mma16(float* d, const uint32_t* a,
                                      uint32_t b0, uint32_t b1) {
    asm volatile("mma.sync.aligned.m16n8k16.row.col.f32.f16.f16.f32 "
                 "{%0,%1,%2,%3}, {%4,%5,%6,%7}, {%8,%9}, {%0,%1,%2,%3};"
                 : "+f"(d[0]), "+f"(d[1]), "+f"(d[2]), "+f"(d[3])
                 : "r"(a[0]), "r"(a[1]), "r"(a[2]), "r"(a[3]), "r"(b0), "r"(b1));
}
__device__ __forceinline__ void cp16(uint32_t dst, const void* src) {
    asm volatile("cp.async.cg.shared.global [%0], [%1], 16;" :: "r"(dst), "l"(src));
}
// exact 2Sum: master += hh; residual * 4096 accumulated into corr; hh = 0.
__device__ __forceinline__ void twosum_acc(float& master, float& corr, float& hh) {
    float a = master, b = hh, s, bp, ap, da, db, r;
    asm("add.rn.f32 %0, %1, %2;" : "=f"(s)  : "f"(a),  "f"(b));
    asm("sub.rn.f32 %0, %1, %2;" : "=f"(bp) : "f"(s),  "f"(a));
    asm("sub.rn.f32 %0, %1, %2;" : "=f"(ap) : "f"(s),  "f"(bp));
    asm("sub.rn.f32 %0, %1, %2;" : "=f"(db) : "f"(b),  "f"(bp));
    asm("sub.rn.f32 %0, %1, %2;" : "=f"(da) : "f"(a),  "f"(ap));
    asm("add.rn.f32 %0, %1, %2;" : "=f"(r)  : "f"(da), "f"(db));
    asm("fma.rn.f32 %0, %1, 0f45800000, %0;" : "+f"(corr) : "f"(r)); // corr += r*4096
    master = s;
    hh = 0.0f;
}

// ------------------------- W split (pre-swizzled planes) -------------------
// plane0 = fp16(64w), plane1 = fp16((64w - p0)*2^12), plane2 = fp16(p1*2^-12)
__global__ void wsplit_kernel(const float* __restrict__ W) {
    const int n = blockIdx.x;
    const int k = blockIdx.y * 256 + threadIdx.x;
    const float bp = W[(size_t)n * HIDDEN + k] * 64.0f;
    uint16_t s0, s1;
    split2(bp, s0, s1);
    const uint16_t s2 = f16u(f16f(s1) * (1.0f / 4096.0f));
    const int t    = k >> 5;
    const int pair = (k & 31) >> 1;
    const int half = k & 1;
    const uint32_t v  = (uint32_t)(((n >> 1) & 3) << 2);
    const uint32_t wi = (size_t)t * B_TILE_WORDS + (uint32_t)n * 16u
                        + ((uint32_t)pair ^ v);
    uint16_t* base = (uint16_t*)g_Bsplit;
    base[(size_t)0 * B_PLANE_WORDS * 2 + (size_t)wi * 2 + half] = s0;
    base[(size_t)1 * B_PLANE_WORDS * 2 + (size_t)wi * 2 + half] = s1;
    base[(size_t)2 * B_PLANE_WORDS * 2 + (size_t)wi * 2 + half] = s2;
}

// ------------------------------- GEMM kernel -------------------------------
__global__ __launch_bounds__(NTHR, 1)
void gemm_fp16_kernel(const float* __restrict__ A) {
    extern __shared__ uint32_t sm[];
    const int tid  = threadIdx.x;
    const int wid  = tid >> 5;
    const int lane = tid & 31;
    const int n0   = blockIdx.x * 128;
    const int m0   = blockIdx.y * 128;

    // ---- staging mappings (unchanged from round 7)
    const int r = tid >> 1;
    const int h = tid & 1;
    const float* aPtr = A + (size_t)(m0 + r) * HIDDEN + h * 16;
    const uint32_t vr = (uint32_t)(((r >> 1) & 3) << 2);
    const uint32_t aw0 = (uint32_t)r * 16u + ((uint32_t)(8 * h) ^ vr);
    const uint32_t aw1 = (uint32_t)r * 16u + ((uint32_t)(8 * h + 4) ^ vr);

    const uint32_t bCopyOff = (uint32_t)tid * 8u;
    uint32_t smAddr;
    asm("{ .reg .u64 t; cvta.to.shared.u64 t, %1; cvt.u32.u64 %0, t; }"
        : "=r"(smAddr) : "l"((const void*)sm));

    // ---- frag mappings: warp grid 4m x 2n, warp tile m32 x n64
    const int wm = wid & 3;                   // m quadrant (32 rows)
    const int wn = wid >> 2;                  // n half (64 cols)
    const int qq = lane >> 2;
    const int c  = lane & 3;
    const uint32_t v = (uint32_t)(((qq >> 1) & 3) << 2);
    const uint32_t aRowW = ((uint32_t)wm * 32 + (uint32_t)qq) * 16u;  // frag0; frag1 at +256
    const uint32_t bColW = (uint32_t)wn * 1024u + (uint32_t)qq * 16u;

    // frag index fi = nf*2 + m  (nf: 0..7 n-frags, m: 0..1 m-frags)
    float hh[16][4];
    float corr[16][4];
    float master[16][4];
    #pragma unroll
    for (int fi = 0; fi < 16; fi++)
        #pragma unroll
        for (int j = 0; j < 4; j++) {
            hh[fi][j] = 0.0f; corr[fi][j] = 0.0f; master[fi][j] = 0.0f;
        }

    auto stageA = [&](uint32_t* dst, const float4* pf) {
        uint32_t pk[2][8];
        #pragma unroll
        for (int j = 0; j < 4; j++) {
            const float4 vv = pf[j];
            uint16_t a0, a1, b0, b1, c0, c1, d0, d1;
            split2(vv.x, a0, a1);
            split2(vv.y, b0, b1);
            split2(vv.z, c0, c1);
            split2(vv.w, d0, d1);
            pk[0][j*2]   = (uint32_t)a0 | ((uint32_t)b0 << 16);
            pk[0][j*2+1] = (uint32_t)c0 | ((uint32_t)d0 << 16);
            pk[1][j*2]   = (uint32_t)a1 | ((uint32_t)b1 << 16);
            pk[1][j*2+1] = (uint32_t)c1 | ((uint32_t)d1 << 16);
        }
        #pragma unroll
        for (int p = 0; p < 2; p++) {
            *(uint4*)&dst[p * PLANE + aw0] =
                make_uint4(pk[p][0], pk[p][1], pk[p][2], pk[p][3]);
            *(uint4*)&dst[p * PLANE + aw1] =
                make_uint4(pk[p][4], pk[p][5], pk[p][6], pk[p][7]);
        }
    };
    auto stageB = [&](uint32_t stageByteAddr, int t) {
        #pragma unroll
        for (int p = 0; p < 3; p++) {
            const uint32_t* src = g_Bsplit + (size_t)p * B_PLANE_WORDS
                                + (size_t)t * B_TILE_WORDS + (uint32_t)n0 * 16u
                                + bCopyOff;
            const uint32_t dst = stageByteAddr + (B_OFF + p * PLANE + bCopyOff) * 4u;
            cp16(dst,      src);
            cp16(dst + 16, src + 4);
        }
        asm volatile("cp.async.commit_group;");
    };

    // ---- prologue
    float4 pf[4];
    #pragma unroll
    for (int j = 0; j < 4; j++) pf[j] = *(const float4*)(aPtr + j * 4);
    stageB(smAddr, 0);
    stageA(sm, pf);
    #pragma unroll
    for (int j = 0; j < 4; j++) pf[j] = *(const float4*)(aPtr + KTILE + j * 4);

    #pragma unroll 1
    for (int t = 0; t < NTILES; ++t) {
        uint32_t* S = sm + (t & 1) * STG_WORDS;
        __syncthreads();

        if (t + 1 < NTILES) {
            uint32_t* Sn = sm + ((t + 1) & 1) * STG_WORDS;
            stageB(smAddr + (uint32_t)(((t + 1) & 1) * STG_WORDS) * 4u, t + 1);
            stageA(Sn, pf);
            if (t + 2 < NTILES) {
                const float* ap = aPtr + (size_t)(t + 2) * KTILE;
                #pragma unroll
                for (int j = 0; j < 4; j++) pf[j] = *(const float4*)(ap + j * 4);
            }
            asm volatile("cp.async.wait_group 1;");
        } else {
            asm volatile("cp.async.wait_group 0;");
        }
        __syncthreads();

        // ---- 2 k-steps (k16): per n-frag, 2 m-frags x 4 products
        #pragma unroll
        for (int ks = 0; ks < 2; ks++) {
            const uint32_t o1 = ((uint32_t)(8 * ks + c)) ^ v;
            const uint32_t o2 = o1 ^ 4u;
            uint32_t A0[2][2][4];   // [plane][mfrag][word]
            #pragma unroll
            for (int p = 0; p < 2; p++)
                #pragma unroll
                for (int m = 0; m < 2; m++) {
                    const uint32_t ab = (uint32_t)p * PLANE + aRowW + (uint32_t)m * 256u;
                    A0[p][m][0] = S[ab + o1];
                    A0[p][m][1] = S[ab + 128 + o1];
                    A0[p][m][2] = S[ab + o2];
                    A0[p][m][3] = S[ab + 128 + o2];
                }
            #pragma unroll
            for (int nf = 0; nf < 8; nf++) {
                const uint32_t bb = B_OFF + bColW + (uint32_t)nf * 128u;
                const uint32_t b00 = S[bb + o1];
                const uint32_t b01 = S[bb + o2];
                const uint32_t b10 = S[PLANE + bb + o1];
                const uint32_t b11 = S[PLANE + bb + o2];
                const uint32_t b20 = S[2 * PLANE + bb + o1];
                const uint32_t b21 = S[2 * PLANE + bb + o2];
                #pragma unroll
                for (int m = 0; m < 2; m++) {
                    const int fi = nf * 2 + m;
                    mma16(hh[fi],   A0[0][m], b00, b01); // a0*b0
                    mma16(corr[fi], A0[0][m], b10, b11); // a0*b1
                    mma16(corr[fi], A0[1][m], b00, b01); // a1*b0
                    mma16(corr[fi], A0[1][m], b20, b21); // a1*b1*2^-12
                }
            }
        }

        // ---- exact drain hh -> master every 4 tiles (56x)
        if ((t & 3) == 3) {
            #pragma unroll
            for (int fi = 0; fi < 16; fi++)
                #pragma unroll
                for (int j = 0; j < 4; j++)
                    twosum_acc(master[fi][j], corr[fi][j], hh[fi][j]);
        }
    }

    // ---- epilogue: fp64 combine (undo scales) + sigmoid, direct stores
    #pragma unroll
    for (int fi = 0; fi < 16; fi++) {
        const int nf = fi >> 1;
        const int m  = fi & 1;
        const int r1 = m0 + wm * 32 + m * 16 + qq;
        const int r2 = r1 + 8;
        const int cc = n0 + wn * 64 + nf * 8 + c * 2;
        double lg[4];
        #pragma unroll
        for (int j = 0; j < 4; j++)
            lg[j] = ((double)master[fi][j]
                   + (double)corr[fi][j] * (1.0 / 4096.0)) * (1.0 / 64.0);
        float2 v1, v2;
        v1.x = (float)(1.0 / (1.0 + exp(-lg[0])));
        v1.y = (float)(1.0 / (1.0 + exp(-lg[1])));
        v2.x = (float)(1.0 / (1.0 + exp(-lg[2])));
        v2.y = (float)(1.0 / (1.0 + exp(-lg[3])));
        *(float2*)&g_scores[(size_t)r1 * NEXP + cc] = v1;
        *(float2*)&g_scores[(size_t)r2 * NEXP + cc] = v2;
    }
}

// ----------------------------- Top-k kernel --------------------------------
__global__ __launch_bounds__(256)
void topk_kernel(const float* __restrict__ bias,
                 float* __restrict__ out,
                 int write_idx)
{
    const int warp = threadIdx.x >> 5;
    const int lane = threadIdx.x & 31;
    const int row  = blockIdx.x * 8 + warp;
    if (row >= SEQ) return;

    const float* sp = g_scores + (size_t)row * NEXP + lane * 8;
    const float4 sA = *(const float4*)sp;
    const float4 sB = *(const float4*)(sp + 4);
    float sv[8] = {sA.x, sA.y, sA.z, sA.w, sB.x, sB.y, sB.z, sB.w};

    float c[8];
    #pragma unroll
    for (int i = 0; i < 8; i++)
        c[i] = sv[i] + __ldg(&bias[lane * 8 + i]);

    float m1 = -INFINITY, m2 = -INFINITY;
    #pragma unroll
    for (int i = 0; i < 8; i++) {
        if (c[i] > m1)      { m2 = m1; m1 = c[i]; }
        else if (c[i] > m2) { m2 = c[i]; }
    }
    #pragma unroll
    for (int off = 1; off <= 2; off <<= 1) {
        const float o1 = __shfl_xor_sync(0xFFFFFFFFu, m1, off);
        const float o2 = __shfl_xor_sync(0xFFFFFFFFu, m2, off);
        const float n1 = fmaxf(m1, o1);
        const float n2 = fmaxf(fminf(m1, o1), fmaxf(m2, o2));
        m1 = n1; m2 = n2;
    }
    const float gs = m1 + m2;
    const int   g  = lane >> 2;

    int rank = 0;
    #pragma unroll
    for (int hh = 0; hh < NGROUP; hh++) {
        const float gh = __shfl_sync(0xFFFFFFFFu, gs, hh * 4);
        rank += (gh > gs) || (gh == gs && hh < g);
    }
    const bool sel = (rank < TOPKG);

    float tmp[8];
    #pragma unroll
    for (int i = 0; i < 8; i++)
        tmp[i] = sel ? c[i] : 0.0f;

    float wsel[8];
    int   isel[8];
    float wsum = 0.0f;
    #pragma unroll
    for (int t = 0; t < TOPK; t++) {
        float bv = tmp[0];
        int   bi = 0;
        #pragma unroll
        for (int i = 1; i < 8; i++)
            if (tmp[i] > bv) { bv = tmp[i]; bi = i; }
        int   be   = lane * 8 + bi;
        float braw = sv[bi];
        #pragma unroll
        for (int off = 16; off; off >>= 1) {
            const float ov  = __shfl_xor_sync(0xFFFFFFFFu, bv, off);
            const int   oe  = __shfl_xor_sync(0xFFFFFFFFu, be, off);
            const float orw = __shfl_xor_sync(0xFFFFFFFFu, braw, off);
            if (ov > bv || (ov == bv && oe < be)) { bv = ov; be = oe; braw = orw; }
        }
        wsel[t] = braw;
        isel[t] = be;
        wsum += braw;
        if ((be >> 3) == lane) tmp[be & 7] = -INFINITY;
    }

    const float invd = RSCALE / (wsum + 1e-20f);
    if (lane == 0) {
        #pragma unroll
        for (int t = 0; t < TOPK; t++)
            out[(size_t)row * TOPK + t] = wsel[t] * invd;
        if (write_idx) {
            #pragma unroll
            for (int t = 0; t < TOPK; t++)
                out[(size_t)SEQ * TOPK + (size_t)row * TOPK + t] = (float)isel[t];
        }
    }
}

// ----------------------------- launch --------------------------------------
extern "C" void kernel_launch(void* const* d_in, const int* in_sizes, int n_in,
                              void* d_out, int out_size)
{
    const float* hidden = (const float*)d_in[0];
    const float* weight = (const float*)d_in[1];
    const float* bias   = (const float*)d_in[2];
    for (int i = 0; i < n_in; i++) {
        if (in_sizes[i] == SEQ * HIDDEN)       hidden = (const float*)d_in[i];
        else if (in_sizes[i] == NEXP * HIDDEN) weight = (const float*)d_in[i];
        else if (in_sizes[i] == NEXP)          bias   = (const float*)d_in[i];
    }
    float* out = (float*)d_out;

    cudaFuncSetAttribute(gemm_fp16_kernel,
                         cudaFuncAttributeMaxDynamicSharedMemorySize, SMEM_BYTES);

    wsplit_kernel<<<dim3(NEXP, HIDDEN / 256), 256>>>(weight);
    gemm_fp16_kernel<<<dim3(NEXP / 128, SEQ / 128), NTHR, SMEM_BYTES>>>(hidden);

    const int write_idx = (out_size >= 2 * SEQ * TOPK) ? 1 : 0;
    topk_kernel<<<SEQ / 8, 256>>>(bias, out, write_idx);
}

// round 9
// speedup vs baseline: 3.3262x; 1.0830x over previous
#include <cuda_runtime.h>
#include <cuda_fp16.h>
#include <math.h>
#include <stdint.h>

// ---------------------------------------------------------------------------
// MoEGate (DeepSeek-V3 noaux_tc router) on GB300 sm_103a (compute_103 PTX)
// Round 9: round-8 fp16 2-way-split GEMM with the a1*b1 product DROPPED
//          (contributes ~2e-8 relative — provably negligible): 3 products,
//          768 HMMA/tile, 2 B planes (less LDS + cp.async + smem), and
//          non-volatile mma asm so ptxas can interleave LDS/HMMA.
//          hh = a0*b0 (2Sum-drained exactly every 4 tiles, residual*2^12 ->
//          corr), corr += a0*b1 + a1*b0. Weights scaled by 64.
// ---------------------------------------------------------------------------

#define SEQ     16384
#define HIDDEN  7168
#define NEXP    256
#define NGROUP  8
#define TOPKG   4
#define TOPK    8
#define RSCALE  2.5f

#define KTILE   32
#define NTILES  (HIDDEN / KTILE)     // 224
#define NTHR    256

// ---- scratch -----
__device__ float g_scores[(size_t)SEQ * NEXP];
// B split planes: [2][NTILES][256 cols][16 words]; word = fp16 pair, swizzled
#define B_TILE_WORDS  (256 * 16)                       // 4096
#define B_PLANE_WORDS ((size_t)NTILES * B_TILE_WORDS)  // 917504
__device__ __align__(16) uint32_t g_Bsplit[2 * B_PLANE_WORDS];

// ---- smem stage layout (words) ----
// A planes: p*2048 for p in {0,1}; B planes: B_OFF + p*2048 for p in {0,1}
#define PLANE     2048
#define B_OFF     4096
#define STG_WORDS 8192
#define SMEM_BYTES (2 * STG_WORDS * 4)   // 64 KB

// ------------------------------- helpers -----------------------------------
__device__ __forceinline__ uint16_t f16u(float x) {
    return __half_as_ushort(__float2half_rn(x));
}
__device__ __forceinline__ float f16f(uint16_t u) {
    return __half2float(__ushort_as_half(u));
}
// 2-way fp16 split: x ~= s0 + s1 * 2^-12  (residual ~2^-23 |x|)
__device__ __forceinline__ void split2(float x, uint16_t& s0, uint16_t& s1) {
    s0 = f16u(x);
    const float r = x - f16f(s0);       // exact (Sterbenz)
    s1 = f16u(r * 4096.0f);
}
// NOTE: non-volatile — outputs are registers, lets ptxas schedule freely.
__device__ __forceinline__ void mma16(float* d, const uint32_t* a,
                                      uint32_t b0, uint32_t b1) {
    asm("mma.sync.aligned.m16n8k16.row.col.f32.f16.f16.f32 "
        "{%0,%1,%2,%3}, {%4,%5,%6,%7}, {%8,%9}, {%0,%1,%2,%3};"
        : "+f"(d[0]), "+f"(d[1]), "+f"(d[2]), "+f"(d[3])
        : "r"(a[0]), "r"(a[1]), "r"(a[2]), "r"(a[3]), "r"(b0), "r"(b1));
}
__device__ __forceinline__ void cp16(uint32_t dst, const void* src) {
    asm volatile("cp.async.cg.shared.global [%0], [%1], 16;" :: "r"(dst), "l"(src));
}
// exact 2Sum: master += hh; residual * 4096 accumulated into corr; hh = 0.
__device__ __forceinline__ void twosum_acc(float& master, float& corr, float& hh) {
    float a = master, b = hh, s, bp, ap, da, db, r;
    asm("add.rn.f32 %0, %1, %2;" : "=f"(s)  : "f"(a),  "f"(b));
    asm("sub.rn.f32 %0, %1, %2;" : "=f"(bp) : "f"(s),  "f"(a));
    asm("sub.rn.f32 %0, %1, %2;" : "=f"(ap) : "f"(s),  "f"(bp));
    asm("sub.rn.f32 %0, %1, %2;" : "=f"(db) : "f"(b),  "f"(bp));
    asm("sub.rn.f32 %0, %1, %2;" : "=f"(da) : "f"(a),  "f"(ap));
    asm("add.rn.f32 %0, %1, %2;" : "=f"(r)  : "f"(da), "f"(db));
    asm("fma.rn.f32 %0, %1, 0f45800000, %0;" : "+f"(corr) : "f"(r)); // corr += r*4096
    master = s;
    hh = 0.0f;
}

// ------------------------- W split (pre-swizzled planes) -------------------
// plane0 = fp16(64w), plane1 = fp16((64w - p0)*2^12)
__global__ void wsplit_kernel(const float* __restrict__ W) {
    const int n = blockIdx.x;
    const int k = blockIdx.y * 256 + threadIdx.x;
    const float bp = W[(size_t)n * HIDDEN + k] * 64.0f;
    uint16_t s0, s1;
    split2(bp, s0, s1);
    const int t    = k >> 5;
    const int pair = (k & 31) >> 1;
    const int half = k & 1;
    const uint32_t v  = (uint32_t)(((n >> 1) & 3) << 2);
    const uint32_t wi = (size_t)t * B_TILE_WORDS + (uint32_t)n * 16u
                        + ((uint32_t)pair ^ v);
    uint16_t* base = (uint16_t*)g_Bsplit;
    base[(size_t)0 * B_PLANE_WORDS * 2 + (size_t)wi * 2 + half] = s0;
    base[(size_t)1 * B_PLANE_WORDS * 2 + (size_t)wi * 2 + half] = s1;
}

// ------------------------------- GEMM kernel -------------------------------
__global__ __launch_bounds__(NTHR, 1)
void gemm_fp16_kernel(const float* __restrict__ A) {
    extern __shared__ uint32_t sm[];
    const int tid  = threadIdx.x;
    const int wid  = tid >> 5;
    const int lane = tid & 31;
    const int n0   = blockIdx.x * 128;
    const int m0   = blockIdx.y * 128;

    // ---- staging mappings
    const int r = tid >> 1;
    const int h = tid & 1;
    const float* aPtr = A + (size_t)(m0 + r) * HIDDEN + h * 16;
    const uint32_t vr = (uint32_t)(((r >> 1) & 3) << 2);
    const uint32_t aw0 = (uint32_t)r * 16u + ((uint32_t)(8 * h) ^ vr);
    const uint32_t aw1 = (uint32_t)r * 16u + ((uint32_t)(8 * h + 4) ^ vr);

    const uint32_t bCopyOff = (uint32_t)tid * 8u;
    uint32_t smAddr;
    asm("{ .reg .u64 t; cvta.to.shared.u64 t, %1; cvt.u32.u64 %0, t; }"
        : "=r"(smAddr) : "l"((const void*)sm));

    // ---- frag mappings: warp grid 4m x 2n, warp tile m32 x n64
    const int wm = wid & 3;                   // m quadrant (32 rows)
    const int wn = wid >> 2;                  // n half (64 cols)
    const int qq = lane >> 2;
    const int c  = lane & 3;
    const uint32_t v = (uint32_t)(((qq >> 1) & 3) << 2);
    const uint32_t aRowW = ((uint32_t)wm * 32 + (uint32_t)qq) * 16u;  // frag0; frag1 at +256
    const uint32_t bColW = (uint32_t)wn * 1024u + (uint32_t)qq * 16u;

    // frag index fi = nf*2 + m  (nf: 0..7 n-frags, m: 0..1 m-frags)
    float hh[16][4];
    float corr[16][4];
    float master[16][4];
    #pragma unroll
    for (int fi = 0; fi < 16; fi++)
        #pragma unroll
        for (int j = 0; j < 4; j++) {
            hh[fi][j] = 0.0f; corr[fi][j] = 0.0f; master[fi][j] = 0.0f;
        }

    auto stageA = [&](uint32_t* dst, const float4* pf) {
        uint32_t pk[2][8];
        #pragma unroll
        for (int j = 0; j < 4; j++) {
            const float4 vv = pf[j];
            uint16_t a0, a1, b0, b1, c0, c1, d0, d1;
            split2(vv.x, a0, a1);
            split2(vv.y, b0, b1);
            split2(vv.z, c0, c1);
            split2(vv.w, d0, d1);
            pk[0][j*2]   = (uint32_t)a0 | ((uint32_t)b0 << 16);
            pk[0][j*2+1] = (uint32_t)c0 | ((uint32_t)d0 << 16);
            pk[1][j*2]   = (uint32_t)a1 | ((uint32_t)b1 << 16);
            pk[1][j*2+1] = (uint32_t)c1 | ((uint32_t)d1 << 16);
        }
        #pragma unroll
        for (int p = 0; p < 2; p++) {
            *(uint4*)&dst[p * PLANE + aw0] =
                make_uint4(pk[p][0], pk[p][1], pk[p][2], pk[p][3]);
            *(uint4*)&dst[p * PLANE + aw1] =
                make_uint4(pk[p][4], pk[p][5], pk[p][6], pk[p][7]);
        }
    };
    auto stageB = [&](uint32_t stageByteAddr, int t) {
        #pragma unroll
        for (int p = 0; p < 2; p++) {
            const uint32_t* src = g_Bsplit + (size_t)p * B_PLANE_WORDS
                                + (size_t)t * B_TILE_WORDS + (uint32_t)n0 * 16u
                                + bCopyOff;
            const uint32_t dst = stageByteAddr + (B_OFF + p * PLANE + bCopyOff) * 4u;
            cp16(dst,      src);
            cp16(dst + 16, src + 4);
        }
        asm volatile("cp.async.commit_group;");
    };

    // ---- prologue
    float4 pf[4];
    #pragma unroll
    for (int j = 0; j < 4; j++) pf[j] = *(const float4*)(aPtr + j * 4);
    stageB(smAddr, 0);
    stageA(sm, pf);
    #pragma unroll
    for (int j = 0; j < 4; j++) pf[j] = *(const float4*)(aPtr + KTILE + j * 4);

    #pragma unroll 1
    for (int t = 0; t < NTILES; ++t) {
        uint32_t* S = sm + (t & 1) * STG_WORDS;
        __syncthreads();

        if (t + 1 < NTILES) {
            uint32_t* Sn = sm + ((t + 1) & 1) * STG_WORDS;
            stageB(smAddr + (uint32_t)(((t + 1) & 1) * STG_WORDS) * 4u, t + 1);
            stageA(Sn, pf);
            if (t + 2 < NTILES) {
                const float* ap = aPtr + (size_t)(t + 2) * KTILE;
                #pragma unroll
                for (int j = 0; j < 4; j++) pf[j] = *(const float4*)(ap + j * 4);
            }
            asm volatile("cp.async.wait_group 1;");
        } else {
            asm volatile("cp.async.wait_group 0;");
        }
        __syncthreads();

        // ---- 2 k-steps (k16): per n-frag, 2 m-frags x 3 products
        #pragma unroll
        for (int ks = 0; ks < 2; ks++) {
            const uint32_t o1 = ((uint32_t)(8 * ks + c)) ^ v;
            const uint32_t o2 = o1 ^ 4u;
            uint32_t A0[2][2][4];   // [plane][mfrag][word]
            #pragma unroll
            for (int p = 0; p < 2; p++)
                #pragma unroll
                for (int m = 0; m < 2; m++) {
                    const uint32_t ab = (uint32_t)p * PLANE + aRowW + (uint32_t)m * 256u;
                    A0[p][m][0] = S[ab + o1];
                    A0[p][m][1] = S[ab + 128 + o1];
                    A0[p][m][2] = S[ab + o2];
                    A0[p][m][3] = S[ab + 128 + o2];
                }
            #pragma unroll
            for (int nf = 0; nf < 8; nf++) {
                const uint32_t bb = B_OFF + bColW + (uint32_t)nf * 128u;
                const uint32_t b00 = S[bb + o1];
                const uint32_t b01 = S[bb + o2];
                const uint32_t b10 = S[PLANE + bb + o1];
                const uint32_t b11 = S[PLANE + bb + o2];
                #pragma unroll
                for (int m = 0; m < 2; m++) {
                    const int fi = nf * 2 + m;
                    mma16(hh[fi],   A0[0][m], b00, b01); // a0*b0
                    mma16(corr[fi], A0[0][m], b10, b11); // a0*b1
                    mma16(corr[fi], A0[1][m], b00, b01); // a1*b0
                }
            }
        }

        // ---- exact drain hh -> master every 4 tiles (56x)
        if ((t & 3) == 3) {
            #pragma unroll
            for (int fi = 0; fi < 16; fi++)
                #pragma unroll
                for (int j = 0; j < 4; j++)
                    twosum_acc(master[fi][j], corr[fi][j], hh[fi][j]);
        }
    }

    // ---- epilogue: fp64 combine (undo scales) + sigmoid, direct stores
    #pragma unroll
    for (int fi = 0; fi < 16; fi++) {
        const int nf = fi >> 1;
        const int m  = fi & 1;
        const int r1 = m0 + wm * 32 + m * 16 + qq;
        const int r2 = r1 + 8;
        const int cc = n0 + wn * 64 + nf * 8 + c * 2;
        double lg[4];
        #pragma unroll
        for (int j = 0; j < 4; j++)
            lg[j] = ((double)master[fi][j]
                   + (double)corr[fi][j] * (1.0 / 4096.0)) * (1.0 / 64.0);
        float2 v1, v2;
        v1.x = (float)(1.0 / (1.0 + exp(-lg[0])));
        v1.y = (float)(1.0 / (1.0 + exp(-lg[1])));
        v2.x = (float)(1.0 / (1.0 + exp(-lg[2])));
        v2.y = (float)(1.0 / (1.0 + exp(-lg[3])));
        *(float2*)&g_scores[(size_t)r1 * NEXP + cc] = v1;
        *(float2*)&g_scores[(size_t)r2 * NEXP + cc] = v2;
    }
}

// ----------------------------- Top-k kernel --------------------------------
__global__ __launch_bounds__(256)
void topk_kernel(const float* __restrict__ bias,
                 float* __restrict__ out,
                 int write_idx)
{
    const int warp = threadIdx.x >> 5;
    const int lane = threadIdx.x & 31;
    const int row  = blockIdx.x * 8 + warp;
    if (row >= SEQ) return;

    const float* sp = g_scores + (size_t)row * NEXP + lane * 8;
    const float4 sA = *(const float4*)sp;
    const float4 sB = *(const float4*)(sp + 4);
    float sv[8] = {sA.x, sA.y, sA.z, sA.w, sB.x, sB.y, sB.z, sB.w};

    float c[8];
    #pragma unroll
    for (int i = 0; i < 8; i++)
        c[i] = sv[i] + __ldg(&bias[lane * 8 + i]);

    float m1 = -INFINITY, m2 = -INFINITY;
    #pragma unroll
    for (int i = 0; i < 8; i++) {
        if (c[i] > m1)      { m2 = m1; m1 = c[i]; }
        else if (c[i] > m2) { m2 = c[i]; }
    }
    #pragma unroll
    for (int off = 1; off <= 2; off <<= 1) {
        const float o1 = __shfl_xor_sync(0xFFFFFFFFu, m1, off);
        const float o2 = __shfl_xor_sync(0xFFFFFFFFu, m2, off);
        const float n1 = fmaxf(m1, o1);
        const float n2 = fmaxf(fminf(m1, o1), fmaxf(m2, o2));
        m1 = n1; m2 = n2;
    }
    const float gs = m1 + m2;
    const int   g  = lane >> 2;

    int rank = 0;
    #pragma unroll
    for (int hh = 0; hh < NGROUP; hh++) {
        const float gh = __shfl_sync(0xFFFFFFFFu, gs, hh * 4);
        rank += (gh > gs) || (gh == gs && hh < g);
    }
    const bool sel = (rank < TOPKG);

    float tmp[8];
    #pragma unroll
    for (int i = 0; i < 8; i++)
        tmp[i] = sel ? c[i] : 0.0f;

    float wsel[8];
    int   isel[8];
    float wsum = 0.0f;
    #pragma unroll
    for (int t = 0; t < TOPK; t++) {
        float bv = tmp[0];
        int   bi = 0;
        #pragma unroll
        for (int i = 1; i < 8; i++)
            if (tmp[i] > bv) { bv = tmp[i]; bi = i; }
        int   be   = lane * 8 + bi;
        float braw = sv[bi];
        #pragma unroll
        for (int off = 16; off; off >>= 1) {
            const float ov  = __shfl_xor_sync(0xFFFFFFFFu, bv, off);
            const int   oe  = __shfl_xor_sync(0xFFFFFFFFu, be, off);
            const float orw = __shfl_xor_sync(0xFFFFFFFFu, braw, off);
            if (ov > bv || (ov == bv && oe < be)) { bv = ov; be = oe; braw = orw; }
        }
        wsel[t] = braw;
        isel[t] = be;
        wsum += braw;
        if ((be >> 3) == lane) tmp[be & 7] = -INFINITY;
    }

    const float invd = RSCALE / (wsum + 1e-20f);
    if (lane == 0) {
        #pragma unroll
        for (int t = 0; t < TOPK; t++)
            out[(size_t)row * TOPK + t] = wsel[t] * invd;
        if (write_idx) {
            #pragma unroll
            for (int t = 0; t < TOPK; t++)
                out[(size_t)SEQ * TOPK + (size_t)row * TOPK + t] = (float)isel[t];
        }
    }
}

// ----------------------------- launch --------------------------------------
extern "C" void kernel_launch(void* const* d_in, const int* in_sizes, int n_in,
                              void* d_out, int out_size)
{
    const float* hidden = (const float*)d_in[0];
    const float* weight = (const float*)d_in[1];
    const float* bias   = (const float*)d_in[2];
    for (int i = 0; i < n_in; i++) {
        if (in_sizes[i] == SEQ * HIDDEN)       hidden = (const float*)d_in[i];
        else if (in_sizes[i] == NEXP * HIDDEN) weight = (const float*)d_in[i];
        else if (in_sizes[i] == NEXP)          bias   = (const float*)d_in[i];
    }
    float* out = (float*)d_out;

    cudaFuncSetAttribute(gemm_fp16_kernel,
                         cudaFuncAttributeMaxDynamicSharedMemorySize, SMEM_BYTES);

    wsplit_kernel<<<dim3(NEXP, HIDDEN / 256), 256>>>(weight);
    gemm_fp16_kernel<<<dim3(NEXP / 128, SEQ / 128), NTHR, SMEM_BYTES>>>(hidden);

    const int write_idx = (out_size >= 2 * SEQ * TOPK) ? 1 : 0;
    topk_kernel<<<SEQ / 8, 256>>>(bias, out, write_idx);
}